// round 8
// baseline (speedup 1.0000x reference)
#include <cuda_runtime.h>
#include <cstddef>

#define NN 100000
#define EE 1600000
#define GG 512
#define DD 64

// ---------------- scratch (static __device__, no allocation) ----------------
__device__ __align__(256) float g_h[(size_t)NN * DD];
__device__ __align__(256) float g_a[(size_t)NN * DD];
__device__ __align__(256) float g_z[(size_t)NN * DD];
__device__ __align__(256) float g_degw[NN];
__device__ __align__(256) float g_psum[GG * DD];
__device__ __align__(256) float g_pcnt[GG];
__device__ __align__(256) int   g_cnt[NN];
__device__ __align__(256) int   g_rowstart[NN];
__device__ __align__(256) int   g_cursor[NN];
__device__ __align__(256) int2  g_epack[EE];      // (src, w bits), grouped by dst
__device__ __align__(256) int   g_bsum[512];
__device__ __align__(256) int   g_boff[512];
__device__ __align__(256) int   g_batch[NN];
__device__ __align__(256) int   g_perm[NN];       // nodes sorted by degree
__device__ __align__(256) int   g_dh[64];         // degree histogram (capped)
__device__ __align__(256) int   g_dhoff[64];      // degree-bin cursors
__device__ int   g_eflag;   // nonzero -> edge_index stored as int32
__device__ int   g_bflag;   // nonzero -> batch stored as int32

// ---------------- dtype detection ----------------
__global__ void detect_kernel(const int* __restrict__ ei32,
                              const int* __restrict__ b32,
                              int* __restrict__ eflag, int* __restrict__ bflag) {
    __shared__ int se, sb;
    if (threadIdx.x == 0) { se = 0; sb = 0; }
    __syncthreads();
    int e = 0, b = 0;
    for (int i = threadIdx.x; i < 1024; i += blockDim.x) {
        e |= ei32[2 * i + 1];
        b |= b32[NN / 2 + 2 * i + 1];
    }
    if (e) atomicOr(&se, 1);
    if (b) atomicOr(&sb, 1);
    __syncthreads();
    if (threadIdx.x == 0) { *eflag = se; *bflag = sb; }
}

__global__ void cvt_batch_kernel(const int* __restrict__ b32,
                                 int* __restrict__ batch,
                                 const int* __restrict__ bflag) {
    int n = blockIdx.x * blockDim.x + threadIdx.x;
    if (n >= NN) return;
    batch[n] = (*bflag) ? b32[n] : b32[2 * n];
}

// ---------------- CSR build: histogram of dst ----------------
__global__ void hist_kernel(const int* __restrict__ ei32,
                            int* __restrict__ cnt,
                            const int* __restrict__ eflag) {
    int e = blockIdx.x * blockDim.x + threadIdx.x;
    if (e >= EE) return;
    int d = (*eflag) ? ei32[EE + e] : ei32[2 * ((size_t)EE + e)];
    atomicAdd(&cnt[d], 1);
}

// ---------------- degree-bucket permutation ----------------
__global__ void deghist_kernel(const int* __restrict__ cnt, int* __restrict__ dh) {
    int n = blockIdx.x * blockDim.x + threadIdx.x;
    if (n >= NN) return;
    int d = cnt[n]; if (d > 63) d = 63;
    atomicAdd(&dh[d], 1);
}

__global__ void degscan_kernel(const int* __restrict__ dh, int* __restrict__ dhoff) {
    __shared__ int s[64];
    int i = threadIdx.x;   // 64 threads
    s[i] = dh[i];
    __syncthreads();
    #pragma unroll
    for (int o = 1; o < 64; o <<= 1) {
        int v = (i >= o) ? s[i - o] : 0;
        __syncthreads();
        s[i] += v;
        __syncthreads();
    }
    dhoff[i] = s[i] - dh[i];   // exclusive
}

__global__ void permfill_kernel(const int* __restrict__ cnt,
                                int* __restrict__ dhoff, int* __restrict__ perm) {
    int n = blockIdx.x * blockDim.x + threadIdx.x;
    if (n >= NN) return;
    int d = cnt[n]; if (d > 63) d = 63;
    int pos = atomicAdd(&dhoff[d], 1);
    perm[pos] = n;
}

// ---------------- 3-kernel prefix scan over cnt -> rowstart ----------------
__global__ void scan1_kernel(const int* __restrict__ cnt,
                             int* __restrict__ rowstart, int* __restrict__ bsum) {
    int i = blockIdx.x * 256 + threadIdx.x;
    int v = (i < NN) ? cnt[i] : 0;
    int lane = threadIdx.x & 31, wid = threadIdx.x >> 5;
    int x = v;
    #pragma unroll
    for (int o = 1; o < 32; o <<= 1) {
        int y = __shfl_up_sync(~0u, x, o);
        if (lane >= o) x += y;
    }
    __shared__ int ws[8];
    if (lane == 31) ws[wid] = x;
    __syncthreads();
    if (wid == 0) {
        int y = (lane < 8) ? ws[lane] : 0;
        #pragma unroll
        for (int o = 1; o < 8; o <<= 1) {
            int z = __shfl_up_sync(~0u, y, o);
            if (lane >= o) y += z;
        }
        if (lane < 8) ws[lane] = y;
    }
    __syncthreads();
    int incl = x + (wid > 0 ? ws[wid - 1] : 0);
    if (i < NN) rowstart[i] = incl - v;
    if (threadIdx.x == 255) bsum[blockIdx.x] = incl;
}

__global__ void scan2_kernel(const int* __restrict__ bsum, int* __restrict__ boff,
                             int nblocks) {
    int i = threadIdx.x;  // 512 threads
    int v = (i < nblocks) ? bsum[i] : 0;
    int lane = i & 31, wid = i >> 5;
    int x = v;
    #pragma unroll
    for (int o = 1; o < 32; o <<= 1) {
        int y = __shfl_up_sync(~0u, x, o);
        if (lane >= o) x += y;
    }
    __shared__ int ws[16];
    if (lane == 31) ws[wid] = x;
    __syncthreads();
    if (wid == 0) {
        int y = (lane < 16) ? ws[lane] : 0;
        #pragma unroll
        for (int o = 1; o < 16; o <<= 1) {
            int z = __shfl_up_sync(~0u, y, o);
            if (lane >= o) y += z;
        }
        if (lane < 16) ws[lane] = y;
    }
    __syncthreads();
    int incl = x + (wid > 0 ? ws[wid - 1] : 0);
    if (i < nblocks) boff[i] = incl - v;
}

__global__ void scan3_kernel(int* __restrict__ rowstart, int* __restrict__ cursor,
                             const int* __restrict__ boff) {
    int i = blockIdx.x * 256 + threadIdx.x;
    if (i >= NN) return;
    int r = rowstart[i] + boff[blockIdx.x];
    rowstart[i] = r;
    cursor[i] = r;
}

// ---------------- CSR fill: epack[pos] = (src, w) grouped by dst ----------------
__global__ void fill_kernel(const int* __restrict__ ei32,
                            const float* __restrict__ ea,
                            int* __restrict__ cursor,
                            int2* __restrict__ epack,
                            const int* __restrict__ eflag) {
    int e = blockIdx.x * blockDim.x + threadIdx.x;
    if (e >= EE) return;
    int s, d;
    if (*eflag) {
        s = ei32[e];
        d = ei32[EE + e];
    } else {
        s = ei32[2 * (size_t)e];
        d = ei32[2 * ((size_t)EE + e)];
    }
    int pos = atomicAdd(&cursor[d], 1);
    epack[pos] = make_int2(s, __float_as_int(ea[e]));
}

// ---------------- deg_w from CSR (no atomics) ----------------
__global__ void degw_kernel(const int* __restrict__ rowstart,
                            const int* __restrict__ cnt,
                            const int2* __restrict__ epack,
                            float* __restrict__ degw) {
    int n = blockIdx.x * blockDim.x + threadIdx.x;
    if (n >= NN) return;
    int s = rowstart[n], c = cnt[n];
    float sum = 0.f;
    for (int j = 0; j < c; j++) sum += __int_as_float(epack[s + j].y);
    degw[n] = sum;
}

// ---------------- h = x @ W_emb + b_emb ----------------
__global__ void embed_kernel(const float* __restrict__ x,
                             const float* __restrict__ Wemb,
                             const float* __restrict__ bemb,
                             float* __restrict__ h) {
    int t = blockIdx.x * blockDim.x + threadIdx.x;
    if (t >= NN * 16) return;
    int n = t >> 4;
    int q = t & 15;
    float4 xv = ((const float4*)x)[n];
    const float4* W4 = (const float4*)Wemb;
    float4 w0 = W4[0 * 16 + q];
    float4 w1 = W4[1 * 16 + q];
    float4 w2 = W4[2 * 16 + q];
    float4 w3 = W4[3 * 16 + q];
    float4 bb = ((const float4*)bemb)[q];
    float4 o;
    o.x = bb.x + xv.x * w0.x + xv.y * w1.x + xv.z * w2.x + xv.w * w3.x;
    o.y = bb.y + xv.x * w0.y + xv.y * w1.y + xv.z * w2.y + xv.w * w3.y;
    o.z = bb.z + xv.x * w0.z + xv.y * w1.z + xv.z * w2.z + xv.w * w3.z;
    o.w = bb.w + xv.x * w0.w + xv.y * w1.w + xv.z * w2.w + xv.w * w3.w;
    ((float4*)h)[(size_t)n * 16 + q] = o;
}

// ---------------- fused per-layer GEMMs (f32x2 packed) ----------------
// a = h@W1 + b1 ; z = h@W3 + b3 - deg_w ⊙ (h@W2)   (z stored evict-first)
__global__ __launch_bounds__(512) void gemm3_kernel(
    const float* __restrict__ h,
    const float* __restrict__ W1, const float* __restrict__ b1,
    const float* __restrict__ W2,
    const float* __restrict__ W3, const float* __restrict__ b3,
    const float* __restrict__ degw,
    float* __restrict__ a_out, float* __restrict__ z_out) {
    __shared__ __align__(16) float hT[64][128];
    __shared__ __align__(16) float sW[64][64];
    const int tid = threadIdx.x;
    const int nodeBase = blockIdx.x * 128;

    {
        const int n = tid & 127;
        const int kq = tid >> 7;
        const int gn = nodeBase + n;
        #pragma unroll
        for (int kk = 0; kk < 4; kk++) {
            const int k4 = kq * 16 + kk * 4;
            float4 v = make_float4(0.f, 0.f, 0.f, 0.f);
            if (gn < NN) v = *(const float4*)(h + (size_t)gn * 64 + k4);
            hT[k4 + 0][n] = v.x;
            hT[k4 + 1][n] = v.y;
            hT[k4 + 2][n] = v.z;
            hT[k4 + 3][n] = v.w;
        }
    }

    const int tx = tid & 63;
    const int ty = tid >> 6;
    const int nb = ty * 16;

    unsigned long long bacc[8];

    #pragma unroll 1
    for (int m = 0; m < 3; m++) {
        const float* Wm = (m == 0) ? W1 : (m == 1) ? W2 : W3;
        __syncthreads();
        #pragma unroll
        for (int i = 0; i < 2; i++)
            ((float4*)sW)[tid + i * 512] = ((const float4*)Wm)[tid + i * 512];
        __syncthreads();

        unsigned long long acc[8];
        #pragma unroll
        for (int p = 0; p < 8; p++) acc[p] = 0ULL;

        #pragma unroll 8
        for (int k = 0; k < 64; k++) {
            float w = sW[k][tx];
            unsigned long long ws;
            asm("mov.b64 %0, {%1, %1};" : "=l"(ws) : "f"(w));
            #pragma unroll
            for (int i = 0; i < 4; i++) {
                ulonglong2 hv = *(const ulonglong2*)&hT[k][nb + 4 * i];
                asm("fma.rn.f32x2 %0, %1, %2, %0;" : "+l"(acc[2 * i])     : "l"(ws), "l"(hv.x));
                asm("fma.rn.f32x2 %0, %1, %2, %0;" : "+l"(acc[2 * i + 1]) : "l"(ws), "l"(hv.y));
            }
        }

        if (m == 0) {
            const float bias = b1[tx];
            #pragma unroll
            for (int p = 0; p < 8; p++) {
                float f0, f1;
                asm("mov.b64 {%0, %1}, %2;" : "=f"(f0), "=f"(f1) : "l"(acc[p]));
                const int n = nodeBase + nb + 2 * p;
                if (n < NN)     a_out[(size_t)n * 64 + tx]       = f0 + bias;
                if (n + 1 < NN) a_out[(size_t)(n + 1) * 64 + tx] = f1 + bias;
            }
        } else if (m == 1) {
            #pragma unroll
            for (int p = 0; p < 8; p++) bacc[p] = acc[p];
        } else {
            const float bias = b3[tx];
            #pragma unroll
            for (int p = 0; p < 8; p++) {
                float f0, f1, g0, g1;
                asm("mov.b64 {%0, %1}, %2;" : "=f"(f0), "=f"(f1) : "l"(acc[p]));
                asm("mov.b64 {%0, %1}, %2;" : "=f"(g0), "=f"(g1) : "l"(bacc[p]));
                const int n = nodeBase + nb + 2 * p;
                if (n < NN) {
                    float dw = degw[n];
                    __stcs(&z_out[(size_t)n * 64 + tx], f0 + bias - dw * g0);
                }
                if (n + 1 < NN) {
                    float dw = degw[n + 1];
                    __stcs(&z_out[(size_t)(n + 1) * 64 + tx], f1 + bias - dw * g1);
                }
            }
        }
    }
}

// ---------------- gather: h[n] = relu(z[n] + sum_{e->n} w_e * a[src_e]) ----------------
// Nodes processed in degree-sorted order (perm) -> near-zero warp divergence.
// 8 lanes per node, 4-edge unroll -> 8 row loads in flight per thread.
__global__ __launch_bounds__(256) void gather_kernel(
                              const int* __restrict__ perm,
                              const int* __restrict__ rowstart,
                              const int* __restrict__ cnt,
                              const int2* __restrict__ epack,
                              const float* __restrict__ a,
                              const float* __restrict__ z,
                              float* __restrict__ h,
                              const int* __restrict__ batch,
                              float* __restrict__ psum,
                              float* __restrict__ pcnt,
                              int do_pool) {
    int t = blockIdx.x * blockDim.x + threadIdx.x;
    int idx = t >> 3;
    if (idx >= NN) return;
    int n = __ldg(perm + idx);
    int lane = t & 7;          // 8 floats each (2 float4)
    int s = __ldg(rowstart + n);
    int c = __ldg(cnt + n);
    const float4* a4 = (const float4*)a;

    const float4* zp4 = (const float4*)z + (size_t)n * 16 + lane * 2;
    float4 acc0 = __ldcs(zp4);
    float4 acc1 = __ldcs(zp4 + 1);

    int j = 0;
    for (; j + 4 <= c; j += 4) {
        int2 p0 = __ldg(epack + s + j);
        int2 p1 = __ldg(epack + s + j + 1);
        int2 p2 = __ldg(epack + s + j + 2);
        int2 p3 = __ldg(epack + s + j + 3);
        const float4* r0 = a4 + (size_t)p0.x * 16 + lane * 2;
        const float4* r1 = a4 + (size_t)p1.x * 16 + lane * 2;
        const float4* r2 = a4 + (size_t)p2.x * 16 + lane * 2;
        const float4* r3 = a4 + (size_t)p3.x * 16 + lane * 2;
        float4 v00 = __ldg(r0), v01 = __ldg(r0 + 1);
        float4 v10 = __ldg(r1), v11 = __ldg(r1 + 1);
        float4 v20 = __ldg(r2), v21 = __ldg(r2 + 1);
        float4 v30 = __ldg(r3), v31 = __ldg(r3 + 1);
        float w0 = __int_as_float(p0.y);
        float w1 = __int_as_float(p1.y);
        float w2 = __int_as_float(p2.y);
        float w3 = __int_as_float(p3.y);
        acc0.x = fmaf(w0, v00.x, acc0.x); acc0.y = fmaf(w0, v00.y, acc0.y);
        acc0.z = fmaf(w0, v00.z, acc0.z); acc0.w = fmaf(w0, v00.w, acc0.w);
        acc1.x = fmaf(w0, v01.x, acc1.x); acc1.y = fmaf(w0, v01.y, acc1.y);
        acc1.z = fmaf(w0, v01.z, acc1.z); acc1.w = fmaf(w0, v01.w, acc1.w);
        acc0.x = fmaf(w1, v10.x, acc0.x); acc0.y = fmaf(w1, v10.y, acc0.y);
        acc0.z = fmaf(w1, v10.z, acc0.z); acc0.w = fmaf(w1, v10.w, acc0.w);
        acc1.x = fmaf(w1, v11.x, acc1.x); acc1.y = fmaf(w1, v11.y, acc1.y);
        acc1.z = fmaf(w1, v11.z, acc1.z); acc1.w = fmaf(w1, v11.w, acc1.w);
        acc0.x = fmaf(w2, v20.x, acc0.x); acc0.y = fmaf(w2, v20.y, acc0.y);
        acc0.z = fmaf(w2, v20.z, acc0.z); acc0.w = fmaf(w2, v20.w, acc0.w);
        acc1.x = fmaf(w2, v21.x, acc1.x); acc1.y = fmaf(w2, v21.y, acc1.y);
        acc1.z = fmaf(w2, v21.z, acc1.z); acc1.w = fmaf(w2, v21.w, acc1.w);
        acc0.x = fmaf(w3, v30.x, acc0.x); acc0.y = fmaf(w3, v30.y, acc0.y);
        acc0.z = fmaf(w3, v30.z, acc0.z); acc0.w = fmaf(w3, v30.w, acc0.w);
        acc1.x = fmaf(w3, v31.x, acc1.x); acc1.y = fmaf(w3, v31.y, acc1.y);
        acc1.z = fmaf(w3, v31.z, acc1.z); acc1.w = fmaf(w3, v31.w, acc1.w);
    }
    for (; j < c; j++) {
        int2 p0 = __ldg(epack + s + j);
        float w0 = __int_as_float(p0.y);
        const float4* r0 = a4 + (size_t)p0.x * 16 + lane * 2;
        float4 v00 = __ldg(r0);
        float4 v01 = __ldg(r0 + 1);
        acc0.x = fmaf(w0, v00.x, acc0.x); acc0.y = fmaf(w0, v00.y, acc0.y);
        acc0.z = fmaf(w0, v00.z, acc0.z); acc0.w = fmaf(w0, v00.w, acc0.w);
        acc1.x = fmaf(w0, v01.x, acc1.x); acc1.y = fmaf(w0, v01.y, acc1.y);
        acc1.z = fmaf(w0, v01.z, acc1.z); acc1.w = fmaf(w0, v01.w, acc1.w);
    }

    acc0.x = fmaxf(acc0.x, 0.f); acc0.y = fmaxf(acc0.y, 0.f);
    acc0.z = fmaxf(acc0.z, 0.f); acc0.w = fmaxf(acc0.w, 0.f);
    acc1.x = fmaxf(acc1.x, 0.f); acc1.y = fmaxf(acc1.y, 0.f);
    acc1.z = fmaxf(acc1.z, 0.f); acc1.w = fmaxf(acc1.w, 0.f);
    float4* hp4 = (float4*)h + (size_t)n * 16 + lane * 2;
    hp4[0] = acc0;
    hp4[1] = acc1;

    if (do_pool) {
        int g = __ldg(batch + n);
        float* p = psum + (size_t)g * 64 + lane * 8;
        asm volatile("red.global.add.v4.f32 [%0], {%1, %2, %3, %4};"
                     :: "l"(p), "f"(acc0.x), "f"(acc0.y), "f"(acc0.z), "f"(acc0.w) : "memory");
        asm volatile("red.global.add.v4.f32 [%0], {%1, %2, %3, %4};"
                     :: "l"(p + 4), "f"(acc1.x), "f"(acc1.y), "f"(acc1.z), "f"(acc1.w) : "memory");
        if (lane == 0)
            asm volatile("red.global.add.f32 [%0], %1;" :: "l"(pcnt + g), "f"(1.0f) : "memory");
    }
}

// ---------------- final MLP head ----------------
__global__ void mlp_kernel(const float* __restrict__ psum,
                           const float* __restrict__ pcnt,
                           const float* __restrict__ Wl1, const float* __restrict__ bl1,
                           const float* __restrict__ Wl2, const float* __restrict__ bl2,
                           float* __restrict__ out) {
    __shared__ float sW1[64 * 32];
    __shared__ float sW2[32 * 3];
    __shared__ float sb1[32];
    __shared__ float sb2[3];
    int tid = threadIdx.x;
    for (int i = tid; i < 64 * 32; i += blockDim.x) sW1[i] = Wl1[i];
    for (int i = tid; i < 32 * 3; i += blockDim.x) sW2[i] = Wl2[i];
    if (tid < 32) sb1[tid] = bl1[tid];
    if (tid < 3) sb2[tid] = bl2[tid];
    __syncthreads();

    int g = blockIdx.x * blockDim.x + tid;
    if (g >= GG) return;
    float inv = 1.0f / fmaxf(pcnt[g], 1.0f);
    float hid[32];
    #pragma unroll
    for (int j = 0; j < 32; j++) hid[j] = sb1[j];
    #pragma unroll 8
    for (int k = 0; k < 64; k++) {
        float xv = psum[(size_t)g * 64 + k] * inv;
        #pragma unroll
        for (int j = 0; j < 32; j++) hid[j] += xv * sW1[k * 32 + j];
    }
    #pragma unroll
    for (int j = 0; j < 32; j++) hid[j] = fmaxf(hid[j], 0.f);
    #pragma unroll
    for (int c = 0; c < 3; c++) {
        float o = sb2[c];
        #pragma unroll
        for (int j = 0; j < 32; j++) o += hid[j] * sW2[j * 3 + c];
        out[g * 3 + c] = o;
    }
}

// ---------------- launch ----------------
extern "C" void kernel_launch(void* const* d_in, const int* in_sizes, int n_in,
                              void* d_out, int out_size) {
    const float* x        = (const float*)d_in[0];
    const int*   ei32     = (const int*)d_in[1];
    const float* ea       = (const float*)d_in[2];
    const int*   b32      = (const int*)d_in[3];
    const float* Wemb     = (const float*)d_in[4];
    const float* bemb     = (const float*)d_in[5];
    const float* W1       = (const float*)d_in[6];
    const float* b1       = (const float*)d_in[7];
    const float* W2       = (const float*)d_in[8];
    const float* W3       = (const float*)d_in[9];
    const float* b3       = (const float*)d_in[10];
    const float* Wl1      = (const float*)d_in[11];
    const float* bl1      = (const float*)d_in[12];
    const float* Wl2      = (const float*)d_in[13];
    const float* bl2      = (const float*)d_in[14];
    float* out = (float*)d_out;

    float *hp, *ap, *zp, *dwp, *psp, *pcp;
    int *cntp, *rsp, *curp, *bsp, *bop, *bp, *efp, *bfp, *permp, *dhp, *dhop;
    int2* epp;
    cudaGetSymbolAddress((void**)&hp, g_h);
    cudaGetSymbolAddress((void**)&ap, g_a);
    cudaGetSymbolAddress((void**)&zp, g_z);
    cudaGetSymbolAddress((void**)&dwp, g_degw);
    cudaGetSymbolAddress((void**)&psp, g_psum);
    cudaGetSymbolAddress((void**)&pcp, g_pcnt);
    cudaGetSymbolAddress((void**)&cntp, g_cnt);
    cudaGetSymbolAddress((void**)&rsp, g_rowstart);
    cudaGetSymbolAddress((void**)&curp, g_cursor);
    cudaGetSymbolAddress((void**)&bsp, g_bsum);
    cudaGetSymbolAddress((void**)&bop, g_boff);
    cudaGetSymbolAddress((void**)&epp, g_epack);
    cudaGetSymbolAddress((void**)&bp, g_batch);
    cudaGetSymbolAddress((void**)&permp, g_perm);
    cudaGetSymbolAddress((void**)&dhp, g_dh);
    cudaGetSymbolAddress((void**)&dhop, g_dhoff);
    cudaGetSymbolAddress((void**)&efp, g_eflag);
    cudaGetSymbolAddress((void**)&bfp, g_bflag);

    cudaMemsetAsync(cntp, 0, NN * sizeof(int));
    cudaMemsetAsync(dhp, 0, 64 * sizeof(int));
    cudaMemsetAsync(psp, 0, GG * DD * sizeof(float));
    cudaMemsetAsync(pcp, 0, GG * sizeof(float));

    const int scanBlocks = (NN + 255) / 256;   // 391

    detect_kernel<<<1, 256>>>(ei32, b32, efp, bfp);
    cvt_batch_kernel<<<(NN + 255) / 256, 256>>>(b32, bp, bfp);
    hist_kernel<<<(EE + 255) / 256, 256>>>(ei32, cntp, efp);
    deghist_kernel<<<(NN + 255) / 256, 256>>>(cntp, dhp);
    degscan_kernel<<<1, 64>>>(dhp, dhop);
    permfill_kernel<<<(NN + 255) / 256, 256>>>(cntp, dhop, permp);
    scan1_kernel<<<scanBlocks, 256>>>(cntp, rsp, bsp);
    scan2_kernel<<<1, 512>>>(bsp, bop, scanBlocks);
    scan3_kernel<<<scanBlocks, 256>>>(rsp, curp, bop);
    fill_kernel<<<(EE + 255) / 256, 256>>>(ei32, ea, curp, epp, efp);
    degw_kernel<<<(NN + 255) / 256, 256>>>(rsp, cntp, epp, dwp);

    embed_kernel<<<(NN * 16 + 255) / 256, 256>>>(x, Wemb, bemb, hp);

    const int gemmBlocks = (NN + 127) / 128;
    const int gatherBlocks = (NN * 8 + 255) / 256;

    for (int l = 0; l < 3; l++) {
        gemm3_kernel<<<gemmBlocks, 512>>>(hp,
                                          W1 + (size_t)l * DD * DD, b1 + (size_t)l * DD,
                                          W2 + (size_t)l * DD * DD,
                                          W3 + (size_t)l * DD * DD, b3 + (size_t)l * DD,
                                          dwp, ap, zp);
        gather_kernel<<<gatherBlocks, 256>>>(permp, rsp, cntp, epp, ap, zp, hp,
                                             bp, psp, pcp, (l == 2) ? 1 : 0);
    }

    mlp_kernel<<<2, 256>>>(psp, pcp, Wl1, bl1, Wl2, bl2, out);
}

// round 9
// speedup vs baseline: 1.5995x; 1.5995x over previous
#include <cuda_runtime.h>
#include <cstddef>

#define NN 100000
#define EE 1600000
#define GG 512
#define DD 64

// ---------------- scratch (static __device__, no allocation) ----------------
__device__ __align__(256) float g_h[(size_t)NN * DD];
__device__ __align__(256) float g_a[(size_t)NN * DD];
__device__ __align__(256) float g_z[(size_t)NN * DD];
__device__ __align__(256) float g_degw[NN];
__device__ __align__(256) float g_psum[GG * DD];
__device__ __align__(256) float g_pcnt[GG];
__device__ __align__(256) int   g_cnt[NN];
__device__ __align__(256) int   g_rowstart[NN];
__device__ __align__(256) int   g_cursor[NN];
__device__ __align__(256) int2  g_epack[EE];      // (src, w bits), grouped by dst
__device__ __align__(256) int   g_bsum[512];
__device__ __align__(256) int   g_boff[512];
__device__ __align__(256) int   g_batch[NN];
__device__ int   g_eflag;   // nonzero -> edge_index stored as int32
__device__ int   g_bflag;   // nonzero -> batch stored as int32

// ---------------- dtype detection ----------------
__global__ void detect_kernel(const int* __restrict__ ei32,
                              const int* __restrict__ b32,
                              int* __restrict__ eflag, int* __restrict__ bflag) {
    __shared__ int se, sb;
    if (threadIdx.x == 0) { se = 0; sb = 0; }
    __syncthreads();
    int e = 0, b = 0;
    for (int i = threadIdx.x; i < 1024; i += blockDim.x) {
        e |= ei32[2 * i + 1];
        b |= b32[NN / 2 + 2 * i + 1];
    }
    if (e) atomicOr(&se, 1);
    if (b) atomicOr(&sb, 1);
    __syncthreads();
    if (threadIdx.x == 0) { *eflag = se; *bflag = sb; }
}

__global__ void cvt_batch_kernel(const int* __restrict__ b32,
                                 int* __restrict__ batch,
                                 const int* __restrict__ bflag) {
    int n = blockIdx.x * blockDim.x + threadIdx.x;
    if (n >= NN) return;
    batch[n] = (*bflag) ? b32[n] : b32[2 * n];
}

// ---------------- CSR build: histogram of dst ----------------
__global__ void hist_kernel(const int* __restrict__ ei32,
                            int* __restrict__ cnt,
                            const int* __restrict__ eflag) {
    int e = blockIdx.x * blockDim.x + threadIdx.x;
    if (e >= EE) return;
    int d = (*eflag) ? ei32[EE + e] : ei32[2 * ((size_t)EE + e)];
    atomicAdd(&cnt[d], 1);
}

// ---------------- 3-kernel prefix scan over cnt -> rowstart ----------------
__global__ void scan1_kernel(const int* __restrict__ cnt,
                             int* __restrict__ rowstart, int* __restrict__ bsum) {
    int i = blockIdx.x * 256 + threadIdx.x;
    int v = (i < NN) ? cnt[i] : 0;
    int lane = threadIdx.x & 31, wid = threadIdx.x >> 5;
    int x = v;
    #pragma unroll
    for (int o = 1; o < 32; o <<= 1) {
        int y = __shfl_up_sync(~0u, x, o);
        if (lane >= o) x += y;
    }
    __shared__ int ws[8];
    if (lane == 31) ws[wid] = x;
    __syncthreads();
    if (wid == 0) {
        int y = (lane < 8) ? ws[lane] : 0;
        #pragma unroll
        for (int o = 1; o < 8; o <<= 1) {
            int z = __shfl_up_sync(~0u, y, o);
            if (lane >= o) y += z;
        }
        if (lane < 8) ws[lane] = y;
    }
    __syncthreads();
    int incl = x + (wid > 0 ? ws[wid - 1] : 0);
    if (i < NN) rowstart[i] = incl - v;
    if (threadIdx.x == 255) bsum[blockIdx.x] = incl;
}

__global__ void scan2_kernel(const int* __restrict__ bsum, int* __restrict__ boff,
                             int nblocks) {
    int i = threadIdx.x;  // 512 threads
    int v = (i < nblocks) ? bsum[i] : 0;
    int lane = i & 31, wid = i >> 5;
    int x = v;
    #pragma unroll
    for (int o = 1; o < 32; o <<= 1) {
        int y = __shfl_up_sync(~0u, x, o);
        if (lane >= o) x += y;
    }
    __shared__ int ws[16];
    if (lane == 31) ws[wid] = x;
    __syncthreads();
    if (wid == 0) {
        int y = (lane < 16) ? ws[lane] : 0;
        #pragma unroll
        for (int o = 1; o < 16; o <<= 1) {
            int z = __shfl_up_sync(~0u, y, o);
            if (lane >= o) y += z;
        }
        if (lane < 16) ws[lane] = y;
    }
    __syncthreads();
    int incl = x + (wid > 0 ? ws[wid - 1] : 0);
    if (i < nblocks) boff[i] = incl - v;
}

__global__ void scan3_kernel(int* __restrict__ rowstart, int* __restrict__ cursor,
                             const int* __restrict__ boff) {
    int i = blockIdx.x * 256 + threadIdx.x;
    if (i >= NN) return;
    int r = rowstart[i] + boff[blockIdx.x];
    rowstart[i] = r;
    cursor[i] = r;
}

// ---------------- CSR fill: epack[pos] = (src, w) grouped by dst ----------------
__global__ void fill_kernel(const int* __restrict__ ei32,
                            const float* __restrict__ ea,
                            int* __restrict__ cursor,
                            int2* __restrict__ epack,
                            const int* __restrict__ eflag) {
    int e = blockIdx.x * blockDim.x + threadIdx.x;
    if (e >= EE) return;
    int s, d;
    if (*eflag) {
        s = ei32[e];
        d = ei32[EE + e];
    } else {
        s = ei32[2 * (size_t)e];
        d = ei32[2 * ((size_t)EE + e)];
    }
    int pos = atomicAdd(&cursor[d], 1);
    epack[pos] = make_int2(s, __float_as_int(ea[e]));
}

// ---------------- deg_w from CSR (no atomics) ----------------
__global__ void degw_kernel(const int* __restrict__ rowstart,
                            const int* __restrict__ cnt,
                            const int2* __restrict__ epack,
                            float* __restrict__ degw) {
    int n = blockIdx.x * blockDim.x + threadIdx.x;
    if (n >= NN) return;
    int s = rowstart[n], c = cnt[n];
    float sum = 0.f;
    for (int j = 0; j < c; j++) sum += __int_as_float(epack[s + j].y);
    degw[n] = sum;
}

// ---------------- h = x @ W_emb + b_emb ----------------
__global__ void embed_kernel(const float* __restrict__ x,
                             const float* __restrict__ Wemb,
                             const float* __restrict__ bemb,
                             float* __restrict__ h) {
    int t = blockIdx.x * blockDim.x + threadIdx.x;
    if (t >= NN * 16) return;
    int n = t >> 4;
    int q = t & 15;
    float4 xv = ((const float4*)x)[n];
    const float4* W4 = (const float4*)Wemb;
    float4 w0 = W4[0 * 16 + q];
    float4 w1 = W4[1 * 16 + q];
    float4 w2 = W4[2 * 16 + q];
    float4 w3 = W4[3 * 16 + q];
    float4 bb = ((const float4*)bemb)[q];
    float4 o;
    o.x = bb.x + xv.x * w0.x + xv.y * w1.x + xv.z * w2.x + xv.w * w3.x;
    o.y = bb.y + xv.x * w0.y + xv.y * w1.y + xv.z * w2.y + xv.w * w3.y;
    o.z = bb.z + xv.x * w0.z + xv.y * w1.z + xv.z * w2.z + xv.w * w3.z;
    o.w = bb.w + xv.x * w0.w + xv.y * w1.w + xv.z * w2.w + xv.w * w3.w;
    ((float4*)h)[(size_t)n * 16 + q] = o;
}

// ---------------- fused per-layer GEMMs (f32x2 packed) ----------------
// a = h@W1 + b1 ; z = h@W3 + b3 - deg_w ⊙ (h@W2)   (z stored evict-first)
__global__ __launch_bounds__(512) void gemm3_kernel(
    const float* __restrict__ h,
    const float* __restrict__ W1, const float* __restrict__ b1,
    const float* __restrict__ W2,
    const float* __restrict__ W3, const float* __restrict__ b3,
    const float* __restrict__ degw,
    float* __restrict__ a_out, float* __restrict__ z_out) {
    __shared__ __align__(16) float hT[64][128];
    __shared__ __align__(16) float sW[64][64];
    const int tid = threadIdx.x;
    const int nodeBase = blockIdx.x * 128;

    {
        const int n = tid & 127;
        const int kq = tid >> 7;
        const int gn = nodeBase + n;
        #pragma unroll
        for (int kk = 0; kk < 4; kk++) {
            const int k4 = kq * 16 + kk * 4;
            float4 v = make_float4(0.f, 0.f, 0.f, 0.f);
            if (gn < NN) v = *(const float4*)(h + (size_t)gn * 64 + k4);
            hT[k4 + 0][n] = v.x;
            hT[k4 + 1][n] = v.y;
            hT[k4 + 2][n] = v.z;
            hT[k4 + 3][n] = v.w;
        }
    }

    const int tx = tid & 63;
    const int ty = tid >> 6;
    const int nb = ty * 16;

    unsigned long long bacc[8];

    #pragma unroll 1
    for (int m = 0; m < 3; m++) {
        const float* Wm = (m == 0) ? W1 : (m == 1) ? W2 : W3;
        __syncthreads();
        #pragma unroll
        for (int i = 0; i < 2; i++)
            ((float4*)sW)[tid + i * 512] = ((const float4*)Wm)[tid + i * 512];
        __syncthreads();

        unsigned long long acc[8];
        #pragma unroll
        for (int p = 0; p < 8; p++) acc[p] = 0ULL;

        #pragma unroll 8
        for (int k = 0; k < 64; k++) {
            float w = sW[k][tx];
            unsigned long long ws;
            asm("mov.b64 %0, {%1, %1};" : "=l"(ws) : "f"(w));
            #pragma unroll
            for (int i = 0; i < 4; i++) {
                ulonglong2 hv = *(const ulonglong2*)&hT[k][nb + 4 * i];
                asm("fma.rn.f32x2 %0, %1, %2, %0;" : "+l"(acc[2 * i])     : "l"(ws), "l"(hv.x));
                asm("fma.rn.f32x2 %0, %1, %2, %0;" : "+l"(acc[2 * i + 1]) : "l"(ws), "l"(hv.y));
            }
        }

        if (m == 0) {
            const float bias = b1[tx];
            #pragma unroll
            for (int p = 0; p < 8; p++) {
                float f0, f1;
                asm("mov.b64 {%0, %1}, %2;" : "=f"(f0), "=f"(f1) : "l"(acc[p]));
                const int n = nodeBase + nb + 2 * p;
                if (n < NN)     a_out[(size_t)n * 64 + tx]       = f0 + bias;
                if (n + 1 < NN) a_out[(size_t)(n + 1) * 64 + tx] = f1 + bias;
            }
        } else if (m == 1) {
            #pragma unroll
            for (int p = 0; p < 8; p++) bacc[p] = acc[p];
        } else {
            const float bias = b3[tx];
            #pragma unroll
            for (int p = 0; p < 8; p++) {
                float f0, f1, g0, g1;
                asm("mov.b64 {%0, %1}, %2;" : "=f"(f0), "=f"(f1) : "l"(acc[p]));
                asm("mov.b64 {%0, %1}, %2;" : "=f"(g0), "=f"(g1) : "l"(bacc[p]));
                const int n = nodeBase + nb + 2 * p;
                if (n < NN) {
                    float dw = degw[n];
                    __stcs(&z_out[(size_t)n * 64 + tx], f0 + bias - dw * g0);
                }
                if (n + 1 < NN) {
                    float dw = degw[n + 1];
                    __stcs(&z_out[(size_t)(n + 1) * 64 + tx], f1 + bias - dw * g1);
                }
            }
        }
    }
}

// ---------------- gather: h[n] = relu(z[n] + sum_{e->n} w_e * a[src_e]) ----------------
// Natural node order (coalesced z/h/epack streams). 8 lanes per node,
// 4-edge unroll -> 8 independent row loads in flight per thread.
__global__ __launch_bounds__(256) void gather_kernel(
                              const int* __restrict__ rowstart,
                              const int* __restrict__ cnt,
                              const int2* __restrict__ epack,
                              const float* __restrict__ a,
                              const float* __restrict__ z,
                              float* __restrict__ h,
                              const int* __restrict__ batch,
                              float* __restrict__ psum,
                              float* __restrict__ pcnt,
                              int do_pool) {
    int t = blockIdx.x * blockDim.x + threadIdx.x;
    int n = t >> 3;
    if (n >= NN) return;
    int lane = t & 7;          // 8 floats each (2 float4)
    int s = __ldg(rowstart + n);
    int c = __ldg(cnt + n);
    const float4* a4 = (const float4*)a;

    const float4* zp4 = (const float4*)z + (size_t)n * 16 + lane * 2;
    float4 acc0 = __ldcs(zp4);
    float4 acc1 = __ldcs(zp4 + 1);

    int j = 0;
    for (; j + 4 <= c; j += 4) {
        int2 p0 = __ldg(epack + s + j);
        int2 p1 = __ldg(epack + s + j + 1);
        int2 p2 = __ldg(epack + s + j + 2);
        int2 p3 = __ldg(epack + s + j + 3);
        const float4* r0 = a4 + (size_t)p0.x * 16 + lane * 2;
        const float4* r1 = a4 + (size_t)p1.x * 16 + lane * 2;
        const float4* r2 = a4 + (size_t)p2.x * 16 + lane * 2;
        const float4* r3 = a4 + (size_t)p3.x * 16 + lane * 2;
        float4 v00 = __ldg(r0), v01 = __ldg(r0 + 1);
        float4 v10 = __ldg(r1), v11 = __ldg(r1 + 1);
        float4 v20 = __ldg(r2), v21 = __ldg(r2 + 1);
        float4 v30 = __ldg(r3), v31 = __ldg(r3 + 1);
        float w0 = __int_as_float(p0.y);
        float w1 = __int_as_float(p1.y);
        float w2 = __int_as_float(p2.y);
        float w3 = __int_as_float(p3.y);
        acc0.x = fmaf(w0, v00.x, acc0.x); acc0.y = fmaf(w0, v00.y, acc0.y);
        acc0.z = fmaf(w0, v00.z, acc0.z); acc0.w = fmaf(w0, v00.w, acc0.w);
        acc1.x = fmaf(w0, v01.x, acc1.x); acc1.y = fmaf(w0, v01.y, acc1.y);
        acc1.z = fmaf(w0, v01.z, acc1.z); acc1.w = fmaf(w0, v01.w, acc1.w);
        acc0.x = fmaf(w1, v10.x, acc0.x); acc0.y = fmaf(w1, v10.y, acc0.y);
        acc0.z = fmaf(w1, v10.z, acc0.z); acc0.w = fmaf(w1, v10.w, acc0.w);
        acc1.x = fmaf(w1, v11.x, acc1.x); acc1.y = fmaf(w1, v11.y, acc1.y);
        acc1.z = fmaf(w1, v11.z, acc1.z); acc1.w = fmaf(w1, v11.w, acc1.w);
        acc0.x = fmaf(w2, v20.x, acc0.x); acc0.y = fmaf(w2, v20.y, acc0.y);
        acc0.z = fmaf(w2, v20.z, acc0.z); acc0.w = fmaf(w2, v20.w, acc0.w);
        acc1.x = fmaf(w2, v21.x, acc1.x); acc1.y = fmaf(w2, v21.y, acc1.y);
        acc1.z = fmaf(w2, v21.z, acc1.z); acc1.w = fmaf(w2, v21.w, acc1.w);
        acc0.x = fmaf(w3, v30.x, acc0.x); acc0.y = fmaf(w3, v30.y, acc0.y);
        acc0.z = fmaf(w3, v30.z, acc0.z); acc0.w = fmaf(w3, v30.w, acc0.w);
        acc1.x = fmaf(w3, v31.x, acc1.x); acc1.y = fmaf(w3, v31.y, acc1.y);
        acc1.z = fmaf(w3, v31.z, acc1.z); acc1.w = fmaf(w3, v31.w, acc1.w);
    }
    for (; j < c; j++) {
        int2 p0 = __ldg(epack + s + j);
        float w0 = __int_as_float(p0.y);
        const float4* r0 = a4 + (size_t)p0.x * 16 + lane * 2;
        float4 v00 = __ldg(r0);
        float4 v01 = __ldg(r0 + 1);
        acc0.x = fmaf(w0, v00.x, acc0.x); acc0.y = fmaf(w0, v00.y, acc0.y);
        acc0.z = fmaf(w0, v00.z, acc0.z); acc0.w = fmaf(w0, v00.w, acc0.w);
        acc1.x = fmaf(w0, v01.x, acc1.x); acc1.y = fmaf(w0, v01.y, acc1.y);
        acc1.z = fmaf(w0, v01.z, acc1.z); acc1.w = fmaf(w0, v01.w, acc1.w);
    }

    acc0.x = fmaxf(acc0.x, 0.f); acc0.y = fmaxf(acc0.y, 0.f);
    acc0.z = fmaxf(acc0.z, 0.f); acc0.w = fmaxf(acc0.w, 0.f);
    acc1.x = fmaxf(acc1.x, 0.f); acc1.y = fmaxf(acc1.y, 0.f);
    acc1.z = fmaxf(acc1.z, 0.f); acc1.w = fmaxf(acc1.w, 0.f);
    float4* hp4 = (float4*)h + (size_t)n * 16 + lane * 2;
    hp4[0] = acc0;
    hp4[1] = acc1;

    if (do_pool) {
        int g = __ldg(batch + n);
        float* p = psum + (size_t)g * 64 + lane * 8;
        asm volatile("red.global.add.v4.f32 [%0], {%1, %2, %3, %4};"
                     :: "l"(p), "f"(acc0.x), "f"(acc0.y), "f"(acc0.z), "f"(acc0.w) : "memory");
        asm volatile("red.global.add.v4.f32 [%0], {%1, %2, %3, %4};"
                     :: "l"(p + 4), "f"(acc1.x), "f"(acc1.y), "f"(acc1.z), "f"(acc1.w) : "memory");
        if (lane == 0)
            asm volatile("red.global.add.f32 [%0], %1;" :: "l"(pcnt + g), "f"(1.0f) : "memory");
    }
}

// ---------------- final MLP head ----------------
__global__ void mlp_kernel(const float* __restrict__ psum,
                           const float* __restrict__ pcnt,
                           const float* __restrict__ Wl1, const float* __restrict__ bl1,
                           const float* __restrict__ Wl2, const float* __restrict__ bl2,
                           float* __restrict__ out) {
    __shared__ float sW1[64 * 32];
    __shared__ float sW2[32 * 3];
    __shared__ float sb1[32];
    __shared__ float sb2[3];
    int tid = threadIdx.x;
    for (int i = tid; i < 64 * 32; i += blockDim.x) sW1[i] = Wl1[i];
    for (int i = tid; i < 32 * 3; i += blockDim.x) sW2[i] = Wl2[i];
    if (tid < 32) sb1[tid] = bl1[tid];
    if (tid < 3) sb2[tid] = bl2[tid];
    __syncthreads();

    int g = blockIdx.x * blockDim.x + tid;
    if (g >= GG) return;
    float inv = 1.0f / fmaxf(pcnt[g], 1.0f);
    float hid[32];
    #pragma unroll
    for (int j = 0; j < 32; j++) hid[j] = sb1[j];
    #pragma unroll 8
    for (int k = 0; k < 64; k++) {
        float xv = psum[(size_t)g * 64 + k] * inv;
        #pragma unroll
        for (int j = 0; j < 32; j++) hid[j] += xv * sW1[k * 32 + j];
    }
    #pragma unroll
    for (int j = 0; j < 32; j++) hid[j] = fmaxf(hid[j], 0.f);
    #pragma unroll
    for (int c = 0; c < 3; c++) {
        float o = sb2[c];
        #pragma unroll
        for (int j = 0; j < 32; j++) o += hid[j] * sW2[j * 3 + c];
        out[g * 3 + c] = o;
    }
}

// ---------------- launch ----------------
extern "C" void kernel_launch(void* const* d_in, const int* in_sizes, int n_in,
                              void* d_out, int out_size) {
    const float* x        = (const float*)d_in[0];
    const int*   ei32     = (const int*)d_in[1];
    const float* ea       = (const float*)d_in[2];
    const int*   b32      = (const int*)d_in[3];
    const float* Wemb     = (const float*)d_in[4];
    const float* bemb     = (const float*)d_in[5];
    const float* W1       = (const float*)d_in[6];
    const float* b1       = (const float*)d_in[7];
    const float* W2       = (const float*)d_in[8];
    const float* W3       = (const float*)d_in[9];
    const float* b3       = (const float*)d_in[10];
    const float* Wl1      = (const float*)d_in[11];
    const float* bl1      = (const float*)d_in[12];
    const float* Wl2      = (const float*)d_in[13];
    const float* bl2      = (const float*)d_in[14];
    float* out = (float*)d_out;

    float *hp, *ap, *zp, *dwp, *psp, *pcp;
    int *cntp, *rsp, *curp, *bsp, *bop, *bp, *efp, *bfp;
    int2* epp;
    cudaGetSymbolAddress((void**)&hp, g_h);
    cudaGetSymbolAddress((void**)&ap, g_a);
    cudaGetSymbolAddress((void**)&zp, g_z);
    cudaGetSymbolAddress((void**)&dwp, g_degw);
    cudaGetSymbolAddress((void**)&psp, g_psum);
    cudaGetSymbolAddress((void**)&pcp, g_pcnt);
    cudaGetSymbolAddress((void**)&cntp, g_cnt);
    cudaGetSymbolAddress((void**)&rsp, g_rowstart);
    cudaGetSymbolAddress((void**)&curp, g_cursor);
    cudaGetSymbolAddress((void**)&bsp, g_bsum);
    cudaGetSymbolAddress((void**)&bop, g_boff);
    cudaGetSymbolAddress((void**)&epp, g_epack);
    cudaGetSymbolAddress((void**)&bp, g_batch);
    cudaGetSymbolAddress((void**)&efp, g_eflag);
    cudaGetSymbolAddress((void**)&bfp, g_bflag);

    cudaMemsetAsync(cntp, 0, NN * sizeof(int));
    cudaMemsetAsync(psp, 0, GG * DD * sizeof(float));
    cudaMemsetAsync(pcp, 0, GG * sizeof(float));

    const int scanBlocks = (NN + 255) / 256;   // 391

    detect_kernel<<<1, 256>>>(ei32, b32, efp, bfp);
    cvt_batch_kernel<<<(NN + 255) / 256, 256>>>(b32, bp, bfp);
    hist_kernel<<<(EE + 255) / 256, 256>>>(ei32, cntp, efp);
    scan1_kernel<<<scanBlocks, 256>>>(cntp, rsp, bsp);
    scan2_kernel<<<1, 512>>>(bsp, bop, scanBlocks);
    scan3_kernel<<<scanBlocks, 256>>>(rsp, curp, bop);
    fill_kernel<<<(EE + 255) / 256, 256>>>(ei32, ea, curp, epp, efp);
    degw_kernel<<<(NN + 255) / 256, 256>>>(rsp, cntp, epp, dwp);

    embed_kernel<<<(NN * 16 + 255) / 256, 256>>>(x, Wemb, bemb, hp);

    const int gemmBlocks = (NN + 127) / 128;
    const int gatherBlocks = (NN * 8 + 255) / 256;

    for (int l = 0; l < 3; l++) {
        gemm3_kernel<<<gemmBlocks, 512>>>(hp,
                                          W1 + (size_t)l * DD * DD, b1 + (size_t)l * DD,
                                          W2 + (size_t)l * DD * DD,
                                          W3 + (size_t)l * DD * DD, b3 + (size_t)l * DD,
                                          dwp, ap, zp);
        gather_kernel<<<gatherBlocks, 256>>>(rsp, cntp, epp, ap, zp, hp,
                                             bp, psp, pcp, (l == 2) ? 1 : 0);
    }

    mlp_kernel<<<2, 256>>>(psp, pcp, Wl1, bl1, Wl2, bl2, out);
}

// round 10
// speedup vs baseline: 1.6904x; 1.0568x over previous
#include <cuda_runtime.h>
#include <cuda_fp16.h>
#include <cstddef>

#define NN 100000
#define EE 1600000
#define GG 512
#define DD 64

// ---------------- scratch (static __device__, no allocation) ----------------
__device__ __align__(256) float  g_h[(size_t)NN * DD];
__device__ __align__(256) __half g_a[(size_t)NN * DD];   // fp16 rows: 128B each
__device__ __align__(256) float  g_z[(size_t)NN * DD];
__device__ __align__(256) float  g_degw[NN];
__device__ __align__(256) float  g_psum[GG * DD];
__device__ __align__(256) float  g_pcnt[GG];
__device__ __align__(256) int    g_cnt[NN];
__device__ __align__(256) int    g_rowstart[NN];
__device__ __align__(256) int    g_cursor[NN];
__device__ __align__(256) int2   g_epack[EE];     // (src, w bits), grouped by dst
__device__ __align__(256) int    g_bsum[512];
__device__ __align__(256) int    g_boff[512];
__device__ __align__(256) int    g_batch[NN];
__device__ int   g_eflag;   // nonzero -> edge_index stored as int32
__device__ int   g_bflag;   // nonzero -> batch stored as int32

// ---------------- dtype detection ----------------
__global__ void detect_kernel(const int* __restrict__ ei32,
                              const int* __restrict__ b32,
                              int* __restrict__ eflag, int* __restrict__ bflag) {
    __shared__ int se, sb;
    if (threadIdx.x == 0) { se = 0; sb = 0; }
    __syncthreads();
    int e = 0, b = 0;
    for (int i = threadIdx.x; i < 1024; i += blockDim.x) {
        e |= ei32[2 * i + 1];
        b |= b32[NN / 2 + 2 * i + 1];
    }
    if (e) atomicOr(&se, 1);
    if (b) atomicOr(&sb, 1);
    __syncthreads();
    if (threadIdx.x == 0) { *eflag = se; *bflag = sb; }
}

__global__ void cvt_batch_kernel(const int* __restrict__ b32,
                                 int* __restrict__ batch,
                                 const int* __restrict__ bflag) {
    int n = blockIdx.x * blockDim.x + threadIdx.x;
    if (n >= NN) return;
    batch[n] = (*bflag) ? b32[n] : b32[2 * n];
}

// ---------------- CSR build: histogram of dst ----------------
__global__ void hist_kernel(const int* __restrict__ ei32,
                            int* __restrict__ cnt,
                            const int* __restrict__ eflag) {
    int e = blockIdx.x * blockDim.x + threadIdx.x;
    if (e >= EE) return;
    int d = (*eflag) ? ei32[EE + e] : ei32[2 * ((size_t)EE + e)];
    atomicAdd(&cnt[d], 1);
}

// ---------------- 3-kernel prefix scan over cnt -> rowstart ----------------
__global__ void scan1_kernel(const int* __restrict__ cnt,
                             int* __restrict__ rowstart, int* __restrict__ bsum) {
    int i = blockIdx.x * 256 + threadIdx.x;
    int v = (i < NN) ? cnt[i] : 0;
    int lane = threadIdx.x & 31, wid = threadIdx.x >> 5;
    int x = v;
    #pragma unroll
    for (int o = 1; o < 32; o <<= 1) {
        int y = __shfl_up_sync(~0u, x, o);
        if (lane >= o) x += y;
    }
    __shared__ int ws[8];
    if (lane == 31) ws[wid] = x;
    __syncthreads();
    if (wid == 0) {
        int y = (lane < 8) ? ws[lane] : 0;
        #pragma unroll
        for (int o = 1; o < 8; o <<= 1) {
            int z = __shfl_up_sync(~0u, y, o);
            if (lane >= o) y += z;
        }
        if (lane < 8) ws[lane] = y;
    }
    __syncthreads();
    int incl = x + (wid > 0 ? ws[wid - 1] : 0);
    if (i < NN) rowstart[i] = incl - v;
    if (threadIdx.x == 255) bsum[blockIdx.x] = incl;
}

__global__ void scan2_kernel(const int* __restrict__ bsum, int* __restrict__ boff,
                             int nblocks) {
    int i = threadIdx.x;  // 512 threads
    int v = (i < nblocks) ? bsum[i] : 0;
    int lane = i & 31, wid = i >> 5;
    int x = v;
    #pragma unroll
    for (int o = 1; o < 32; o <<= 1) {
        int y = __shfl_up_sync(~0u, x, o);
        if (lane >= o) x += y;
    }
    __shared__ int ws[16];
    if (lane == 31) ws[wid] = x;
    __syncthreads();
    if (wid == 0) {
        int y = (lane < 16) ? ws[lane] : 0;
        #pragma unroll
        for (int o = 1; o < 16; o <<= 1) {
            int z = __shfl_up_sync(~0u, y, o);
            if (lane >= o) y += z;
        }
        if (lane < 16) ws[lane] = y;
    }
    __syncthreads();
    int incl = x + (wid > 0 ? ws[wid - 1] : 0);
    if (i < nblocks) boff[i] = incl - v;
}

__global__ void scan3_kernel(int* __restrict__ rowstart, int* __restrict__ cursor,
                             const int* __restrict__ boff) {
    int i = blockIdx.x * 256 + threadIdx.x;
    if (i >= NN) return;
    int r = rowstart[i] + boff[blockIdx.x];
    rowstart[i] = r;
    cursor[i] = r;
}

// ---------------- CSR fill: epack[pos] = (src, w) grouped by dst ----------------
__global__ void fill_kernel(const int* __restrict__ ei32,
                            const float* __restrict__ ea,
                            int* __restrict__ cursor,
                            int2* __restrict__ epack,
                            const int* __restrict__ eflag) {
    int e = blockIdx.x * blockDim.x + threadIdx.x;
    if (e >= EE) return;
    int s, d;
    if (*eflag) {
        s = ei32[e];
        d = ei32[EE + e];
    } else {
        s = ei32[2 * (size_t)e];
        d = ei32[2 * ((size_t)EE + e)];
    }
    int pos = atomicAdd(&cursor[d], 1);
    epack[pos] = make_int2(s, __float_as_int(ea[e]));
}

// ---------------- deg_w from CSR (no atomics) ----------------
__global__ void degw_kernel(const int* __restrict__ rowstart,
                            const int* __restrict__ cnt,
                            const int2* __restrict__ epack,
                            float* __restrict__ degw) {
    int n = blockIdx.x * blockDim.x + threadIdx.x;
    if (n >= NN) return;
    int s = rowstart[n], c = cnt[n];
    float sum = 0.f;
    for (int j = 0; j < c; j++) sum += __int_as_float(epack[s + j].y);
    degw[n] = sum;
}

// ---------------- h = x @ W_emb + b_emb ----------------
__global__ void embed_kernel(const float* __restrict__ x,
                             const float* __restrict__ Wemb,
                             const float* __restrict__ bemb,
                             float* __restrict__ h) {
    int t = blockIdx.x * blockDim.x + threadIdx.x;
    if (t >= NN * 16) return;
    int n = t >> 4;
    int q = t & 15;
    float4 xv = ((const float4*)x)[n];
    const float4* W4 = (const float4*)Wemb;
    float4 w0 = W4[0 * 16 + q];
    float4 w1 = W4[1 * 16 + q];
    float4 w2 = W4[2 * 16 + q];
    float4 w3 = W4[3 * 16 + q];
    float4 bb = ((const float4*)bemb)[q];
    float4 o;
    o.x = bb.x + xv.x * w0.x + xv.y * w1.x + xv.z * w2.x + xv.w * w3.x;
    o.y = bb.y + xv.x * w0.y + xv.y * w1.y + xv.z * w2.y + xv.w * w3.y;
    o.z = bb.z + xv.x * w0.z + xv.y * w1.z + xv.z * w2.z + xv.w * w3.z;
    o.w = bb.w + xv.x * w0.w + xv.y * w1.w + xv.z * w2.w + xv.w * w3.w;
    ((float4*)h)[(size_t)n * 16 + q] = o;
}

// ---------------- fused per-layer GEMMs (f32x2 packed) ----------------
// a = fp16(h@W1 + b1) ; z = h@W3 + b3 - deg_w ⊙ (h@W2)  (z stored evict-first)
__global__ __launch_bounds__(512) void gemm3_kernel(
    const float* __restrict__ h,
    const float* __restrict__ W1, const float* __restrict__ b1,
    const float* __restrict__ W2,
    const float* __restrict__ W3, const float* __restrict__ b3,
    const float* __restrict__ degw,
    __half* __restrict__ a_out, float* __restrict__ z_out) {
    __shared__ __align__(16) float hT[64][128];
    __shared__ __align__(16) float sW[64][64];
    const int tid = threadIdx.x;
    const int nodeBase = blockIdx.x * 128;

    {
        const int n = tid & 127;
        const int kq = tid >> 7;
        const int gn = nodeBase + n;
        #pragma unroll
        for (int kk = 0; kk < 4; kk++) {
            const int k4 = kq * 16 + kk * 4;
            float4 v = make_float4(0.f, 0.f, 0.f, 0.f);
            if (gn < NN) v = *(const float4*)(h + (size_t)gn * 64 + k4);
            hT[k4 + 0][n] = v.x;
            hT[k4 + 1][n] = v.y;
            hT[k4 + 2][n] = v.z;
            hT[k4 + 3][n] = v.w;
        }
    }

    const int tx = tid & 63;
    const int ty = tid >> 6;
    const int nb = ty * 16;

    unsigned long long bacc[8];

    #pragma unroll 1
    for (int m = 0; m < 3; m++) {
        const float* Wm = (m == 0) ? W1 : (m == 1) ? W2 : W3;
        __syncthreads();
        #pragma unroll
        for (int i = 0; i < 2; i++)
            ((float4*)sW)[tid + i * 512] = ((const float4*)Wm)[tid + i * 512];
        __syncthreads();

        unsigned long long acc[8];
        #pragma unroll
        for (int p = 0; p < 8; p++) acc[p] = 0ULL;

        #pragma unroll 8
        for (int k = 0; k < 64; k++) {
            float w = sW[k][tx];
            unsigned long long ws;
            asm("mov.b64 %0, {%1, %1};" : "=l"(ws) : "f"(w));
            #pragma unroll
            for (int i = 0; i < 4; i++) {
                ulonglong2 hv = *(const ulonglong2*)&hT[k][nb + 4 * i];
                asm("fma.rn.f32x2 %0, %1, %2, %0;" : "+l"(acc[2 * i])     : "l"(ws), "l"(hv.x));
                asm("fma.rn.f32x2 %0, %1, %2, %0;" : "+l"(acc[2 * i + 1]) : "l"(ws), "l"(hv.y));
            }
        }

        if (m == 0) {
            const float bias = b1[tx];
            #pragma unroll
            for (int p = 0; p < 8; p++) {
                float f0, f1;
                asm("mov.b64 {%0, %1}, %2;" : "=f"(f0), "=f"(f1) : "l"(acc[p]));
                const int n = nodeBase + nb + 2 * p;
                if (n < NN)     a_out[(size_t)n * 64 + tx]       = __float2half(f0 + bias);
                if (n + 1 < NN) a_out[(size_t)(n + 1) * 64 + tx] = __float2half(f1 + bias);
            }
        } else if (m == 1) {
            #pragma unroll
            for (int p = 0; p < 8; p++) bacc[p] = acc[p];
        } else {
            const float bias = b3[tx];
            #pragma unroll
            for (int p = 0; p < 8; p++) {
                float f0, f1, g0, g1;
                asm("mov.b64 {%0, %1}, %2;" : "=f"(f0), "=f"(f1) : "l"(acc[p]));
                asm("mov.b64 {%0, %1}, %2;" : "=f"(g0), "=f"(g1) : "l"(bacc[p]));
                const int n = nodeBase + nb + 2 * p;
                if (n < NN) {
                    float dw = degw[n];
                    __stcs(&z_out[(size_t)n * 64 + tx], f0 + bias - dw * g0);
                }
                if (n + 1 < NN) {
                    float dw = degw[n + 1];
                    __stcs(&z_out[(size_t)(n + 1) * 64 + tx], f1 + bias - dw * g1);
                }
            }
        }
    }
}

// ---------------- gather: h[n] = relu(z[n] + sum_{e->n} w_e * fp32(a[src_e])) --------
// fp16 `a` rows = 128B = one cache line. 8 lanes per node, each lane one uint4
// (8 halves) per edge -> a warp instruction covers 4 rows, fully coalesced.
__global__ __launch_bounds__(256) void gather_kernel(
                              const int* __restrict__ rowstart,
                              const int* __restrict__ cnt,
                              const int2* __restrict__ epack,
                              const __half* __restrict__ a,
                              const float* __restrict__ z,
                              float* __restrict__ h,
                              const int* __restrict__ batch,
                              float* __restrict__ psum,
                              float* __restrict__ pcnt,
                              int do_pool) {
    int t = blockIdx.x * blockDim.x + threadIdx.x;
    int n = t >> 3;
    if (n >= NN) return;
    int lane = t & 7;          // 8 floats each (handles dims lane*8 .. lane*8+7)
    int s = __ldg(rowstart + n);
    int c = __ldg(cnt + n);
    const uint4* a4 = (const uint4*)a;   // 8 halves per uint4; 8 uint4 per row

    const float4* zp4 = (const float4*)z + (size_t)n * 16 + lane * 2;
    float4 acc0 = __ldcs(zp4);
    float4 acc1 = __ldcs(zp4 + 1);

    #define ACC_EDGE(V, W) do {                                              \
        const __half2* hv_ = (const __half2*)&(V);                           \
        float2 f0_ = __half22float2(hv_[0]);                                 \
        float2 f1_ = __half22float2(hv_[1]);                                 \
        float2 f2_ = __half22float2(hv_[2]);                                 \
        float2 f3_ = __half22float2(hv_[3]);                                 \
        acc0.x = fmaf((W), f0_.x, acc0.x); acc0.y = fmaf((W), f0_.y, acc0.y);\
        acc0.z = fmaf((W), f1_.x, acc0.z); acc0.w = fmaf((W), f1_.y, acc0.w);\
        acc1.x = fmaf((W), f2_.x, acc1.x); acc1.y = fmaf((W), f2_.y, acc1.y);\
        acc1.z = fmaf((W), f3_.x, acc1.z); acc1.w = fmaf((W), f3_.y, acc1.w);\
    } while (0)

    int j = 0;
    for (; j + 4 <= c; j += 4) {
        int2 p0 = __ldg(epack + s + j);
        int2 p1 = __ldg(epack + s + j + 1);
        int2 p2 = __ldg(epack + s + j + 2);
        int2 p3 = __ldg(epack + s + j + 3);
        uint4 v0 = __ldg(a4 + (size_t)p0.x * 8 + lane);
        uint4 v1 = __ldg(a4 + (size_t)p1.x * 8 + lane);
        uint4 v2 = __ldg(a4 + (size_t)p2.x * 8 + lane);
        uint4 v3 = __ldg(a4 + (size_t)p3.x * 8 + lane);
        float w0 = __int_as_float(p0.y);
        float w1 = __int_as_float(p1.y);
        float w2 = __int_as_float(p2.y);
        float w3 = __int_as_float(p3.y);
        ACC_EDGE(v0, w0);
        ACC_EDGE(v1, w1);
        ACC_EDGE(v2, w2);
        ACC_EDGE(v3, w3);
    }
    for (; j < c; j++) {
        int2 p0 = __ldg(epack + s + j);
        float w0 = __int_as_float(p0.y);
        uint4 v0 = __ldg(a4 + (size_t)p0.x * 8 + lane);
        ACC_EDGE(v0, w0);
    }
    #undef ACC_EDGE

    acc0.x = fmaxf(acc0.x, 0.f); acc0.y = fmaxf(acc0.y, 0.f);
    acc0.z = fmaxf(acc0.z, 0.f); acc0.w = fmaxf(acc0.w, 0.f);
    acc1.x = fmaxf(acc1.x, 0.f); acc1.y = fmaxf(acc1.y, 0.f);
    acc1.z = fmaxf(acc1.z, 0.f); acc1.w = fmaxf(acc1.w, 0.f);
    float4* hp4 = (float4*)h + (size_t)n * 16 + lane * 2;
    hp4[0] = acc0;
    hp4[1] = acc1;

    if (do_pool) {
        int g = __ldg(batch + n);
        float* p = psum + (size_t)g * 64 + lane * 8;
        asm volatile("red.global.add.v4.f32 [%0], {%1, %2, %3, %4};"
                     :: "l"(p), "f"(acc0.x), "f"(acc0.y), "f"(acc0.z), "f"(acc0.w) : "memory");
        asm volatile("red.global.add.v4.f32 [%0], {%1, %2, %3, %4};"
                     :: "l"(p + 4), "f"(acc1.x), "f"(acc1.y), "f"(acc1.z), "f"(acc1.w) : "memory");
        if (lane == 0)
            asm volatile("red.global.add.f32 [%0], %1;" :: "l"(pcnt + g), "f"(1.0f) : "memory");
    }
}

// ---------------- final MLP head ----------------
__global__ void mlp_kernel(const float* __restrict__ psum,
                           const float* __restrict__ pcnt,
                           const float* __restrict__ Wl1, const float* __restrict__ bl1,
                           const float* __restrict__ Wl2, const float* __restrict__ bl2,
                           float* __restrict__ out) {
    __shared__ float sW1[64 * 32];
    __shared__ float sW2[32 * 3];
    __shared__ float sb1[32];
    __shared__ float sb2[3];
    int tid = threadIdx.x;
    for (int i = tid; i < 64 * 32; i += blockDim.x) sW1[i] = Wl1[i];
    for (int i = tid; i < 32 * 3; i += blockDim.x) sW2[i] = Wl2[i];
    if (tid < 32) sb1[tid] = bl1[tid];
    if (tid < 3) sb2[tid] = bl2[tid];
    __syncthreads();

    int g = blockIdx.x * blockDim.x + tid;
    if (g >= GG) return;
    float inv = 1.0f / fmaxf(pcnt[g], 1.0f);
    float hid[32];
    #pragma unroll
    for (int j = 0; j < 32; j++) hid[j] = sb1[j];
    #pragma unroll 8
    for (int k = 0; k < 64; k++) {
        float xv = psum[(size_t)g * 64 + k] * inv;
        #pragma unroll
        for (int j = 0; j < 32; j++) hid[j] += xv * sW1[k * 32 + j];
    }
    #pragma unroll
    for (int j = 0; j < 32; j++) hid[j] = fmaxf(hid[j], 0.f);
    #pragma unroll
    for (int c = 0; c < 3; c++) {
        float o = sb2[c];
        #pragma unroll
        for (int j = 0; j < 32; j++) o += hid[j] * sW2[j * 3 + c];
        out[g * 3 + c] = o;
    }
}

// ---------------- launch ----------------
extern "C" void kernel_launch(void* const* d_in, const int* in_sizes, int n_in,
                              void* d_out, int out_size) {
    const float* x        = (const float*)d_in[0];
    const int*   ei32     = (const int*)d_in[1];
    const float* ea       = (const float*)d_in[2];
    const int*   b32      = (const int*)d_in[3];
    const float* Wemb     = (const float*)d_in[4];
    const float* bemb     = (const float*)d_in[5];
    const float* W1       = (const float*)d_in[6];
    const float* b1       = (const float*)d_in[7];
    const float* W2       = (const float*)d_in[8];
    const float* W3       = (const float*)d_in[9];
    const float* b3       = (const float*)d_in[10];
    const float* Wl1      = (const float*)d_in[11];
    const float* bl1      = (const float*)d_in[12];
    const float* Wl2      = (const float*)d_in[13];
    const float* bl2      = (const float*)d_in[14];
    float* out = (float*)d_out;

    float *hp, *zp, *dwp, *psp, *pcp;
    __half* ap;
    int *cntp, *rsp, *curp, *bsp, *bop, *bp, *efp, *bfp;
    int2* epp;
    cudaGetSymbolAddress((void**)&hp, g_h);
    cudaGetSymbolAddress((void**)&ap, g_a);
    cudaGetSymbolAddress((void**)&zp, g_z);
    cudaGetSymbolAddress((void**)&dwp, g_degw);
    cudaGetSymbolAddress((void**)&psp, g_psum);
    cudaGetSymbolAddress((void**)&pcp, g_pcnt);
    cudaGetSymbolAddress((void**)&cntp, g_cnt);
    cudaGetSymbolAddress((void**)&rsp, g_rowstart);
    cudaGetSymbolAddress((void**)&curp, g_cursor);
    cudaGetSymbolAddress((void**)&bsp, g_bsum);
    cudaGetSymbolAddress((void**)&bop, g_boff);
    cudaGetSymbolAddress((void**)&epp, g_epack);
    cudaGetSymbolAddress((void**)&bp, g_batch);
    cudaGetSymbolAddress((void**)&efp, g_eflag);
    cudaGetSymbolAddress((void**)&bfp, g_bflag);

    cudaMemsetAsync(cntp, 0, NN * sizeof(int));
    cudaMemsetAsync(psp, 0, GG * DD * sizeof(float));
    cudaMemsetAsync(pcp, 0, GG * sizeof(float));

    const int scanBlocks = (NN + 255) / 256;   // 391

    detect_kernel<<<1, 256>>>(ei32, b32, efp, bfp);
    cvt_batch_kernel<<<(NN + 255) / 256, 256>>>(b32, bp, bfp);
    hist_kernel<<<(EE + 255) / 256, 256>>>(ei32, cntp, efp);
    scan1_kernel<<<scanBlocks, 256>>>(cntp, rsp, bsp);
    scan2_kernel<<<1, 512>>>(bsp, bop, scanBlocks);
    scan3_kernel<<<scanBlocks, 256>>>(rsp, curp, bop);
    fill_kernel<<<(EE + 255) / 256, 256>>>(ei32, ea, curp, epp, efp);
    degw_kernel<<<(NN + 255) / 256, 256>>>(rsp, cntp, epp, dwp);

    embed_kernel<<<(NN * 16 + 255) / 256, 256>>>(x, Wemb, bemb, hp);

    const int gemmBlocks = (NN + 127) / 128;
    const int gatherBlocks = (NN * 8 + 255) / 256;

    for (int l = 0; l < 3; l++) {
        gemm3_kernel<<<gemmBlocks, 512>>>(hp,
                                          W1 + (size_t)l * DD * DD, b1 + (size_t)l * DD,
                                          W2 + (size_t)l * DD * DD,
                                          W3 + (size_t)l * DD * DD, b3 + (size_t)l * DD,
                                          dwp, ap, zp);
        gather_kernel<<<gatherBlocks, 256>>>(rsp, cntp, epp, ap, zp, hp,
                                             bp, psp, pcp, (l == 2) ? 1 : 0);
    }

    mlp_kernel<<<2, 256>>>(psp, pcp, Wl1, bl1, Wl2, bl2, out);
}